// round 1
// baseline (speedup 1.0000x reference)
#include <cuda_runtime.h>
#include <cstdio>
#include <math.h>

#define T 8
#define N 20000
#define E 1280000
#define TN (T*N)
#define TE (T*E)

// Scratch (no allocations allowed -> __device__ globals)
__device__ float d_xl[TN*2];   // x @ W_gcn^T
__device__ float d_acc[TN*2];  // scatter accumulator
__device__ int   d_cnt[TN];    // edge-count per dst (deg = cnt+1 with self loop)
__device__ float d_u[TN*3];    // W_ih*(gcn_out) + b_ih + b_hh, interleaved

// ---------------- init: zero accumulators, precompute xl ----------------
__global__ void k_init(const float* __restrict__ x, const float* __restrict__ Wg) {
    int g = blockIdx.x * blockDim.x + threadIdx.x;
    if (g >= TN) return;
    float w00 = Wg[0], w01 = Wg[1], w10 = Wg[2], w11 = Wg[3];
    float x0 = x[2*g], x1 = x[2*g+1];
    d_xl[2*g]   = fmaf(x0, w00, x1*w01);
    d_xl[2*g+1] = fmaf(x0, w10, x1*w11);
    d_acc[2*g] = 0.f; d_acc[2*g+1] = 0.f;
    d_cnt[g] = 0;
}

// ---------------- degree: count edges per dst ----------------
__global__ void k_deg(const int* __restrict__ ei) {
    int idx = blockIdx.x * blockDim.x + threadIdx.x;
    if (idx >= TE) return;
    int t = idx / E, e = idx - t*E;
    int dst = ei[(size_t)t*2*E + E + e];
    atomicAdd(&d_cnt[t*N + dst], 1);
}

// ---------------- messages: norm * xl[src] scattered to dst ----------------
__global__ void k_msg(const int* __restrict__ ei) {
    int idx = blockIdx.x * blockDim.x + threadIdx.x;
    if (idx >= TE) return;
    int t = idx / E, e = idx - t*E;
    const int* eit = ei + (size_t)t*2*E;
    int src = eit[e], dst = eit[E + e];
    int base = t*N;
    float di = rsqrtf((float)(d_cnt[base + src] + 1));
    float dj = rsqrtf((float)(d_cnt[base + dst] + 1));
    float nrm = di * dj;
    float m0 = d_xl[2*(base+src)], m1 = d_xl[2*(base+src)+1];
    atomicAdd(&d_acc[2*(base+dst)],     nrm*m0);
    atomicAdd(&d_acc[2*(base+dst)+1],   nrm*m1);
}

// ---------------- per-node epilogue: self-loop + bias, project to u ----------------
__global__ void k_node(const float* __restrict__ bg, const float* __restrict__ Wih,
                       const float* __restrict__ bih, const float* __restrict__ bhh) {
    int g = blockIdx.x * blockDim.x + threadIdx.x;
    if (g >= TN) return;
    float inv = 1.0f / (float)(d_cnt[g] + 1);   // dinv^2 for self loop
    float g0 = d_acc[2*g]   + inv * d_xl[2*g]   + bg[0];
    float g1 = d_acc[2*g+1] + inv * d_xl[2*g+1] + bg[1];
    #pragma unroll
    for (int m = 0; m < 3; m++)
        d_u[3*g + m] = fmaf(Wih[2*m], g0, fmaf(Wih[2*m+1], g1, bih[m] + bhh[m]));
}

// ---------------- scan ----------------
__device__ __forceinline__ float tanh_fast(float x) {
    float e = __expf(2.0f * x);                 // MUFU.EX2 path
    return 1.0f - __fdividef(2.0f, e + 1.0f);   // MUFU.RCP path
}

__global__ void k_scan(const float* __restrict__ Whh, const float* __restrict__ Wlin,
                       const float* __restrict__ blin, float* __restrict__ out) {
    __shared__ float res[3][3];   // [variant][component]: 0=full, 1=last 4096, 2=last 256
    int tid = threadIdx.x;
    int which = tid >> 5;

    if ((tid & 31) == 0 && which < 3) {
        float w00=Whh[0], w01=Whh[1], w02=Whh[2];
        float w10=Whh[3], w11=Whh[4], w12=Whh[5];
        float w20=Whh[6], w21=Whh[7], w22=Whh[8];
        int start = (which == 0) ? 0 : (which == 1 ? TN - 4096 : TN - 256);
        float h0 = 0.f, h1 = 0.f, h2 = 0.f;

        #define STEP(c0, c1, c2) { \
            float a0 = fmaf(w00,h0, fmaf(w01,h1, fmaf(w02,h2, (c0)))); \
            float a1 = fmaf(w10,h0, fmaf(w11,h1, fmaf(w12,h2, (c1)))); \
            float a2 = fmaf(w20,h0, fmaf(w21,h1, fmaf(w22,h2, (c2)))); \
            h0 = tanh_fast(a0); h1 = tanh_fast(a1); h2 = tanh_fast(a2); }

        #define DO8(B) { \
            float c[24]; \
            _Pragma("unroll") for (int i = 0; i < 6; i++) { \
                c[4*i]=(B)[i].x; c[4*i+1]=(B)[i].y; c[4*i+2]=(B)[i].z; c[4*i+3]=(B)[i].w; } \
            _Pragma("unroll") for (int s = 0; s < 8; s++) { STEP(c[3*s], c[3*s+1], c[3*s+2]); } }

        // start is a multiple of 16 -> 3*start*4 bytes is 16B aligned
        float4 bufA[6], bufB[6];
        {
            const float4* p = reinterpret_cast<const float4*>(d_u + 3*start);
            #pragma unroll
            for (int i = 0; i < 6; i++) bufA[i] = p[i];
        }
        for (int k = start; k < TN; k += 16) {
            // prefetch second half (k+8 <= TN-8, always in-bounds)
            const float4* p1 = reinterpret_cast<const float4*>(d_u + 3*(k+8));
            #pragma unroll
            for (int i = 0; i < 6; i++) bufB[i] = p1[i];
            DO8(bufA);
            if (k + 16 < TN) {
                const float4* p2 = reinterpret_cast<const float4*>(d_u + 3*(k+16));
                #pragma unroll
                for (int i = 0; i < 6; i++) bufA[i] = p2[i];
            }
            DO8(bufB);
        }
        res[which][0] = h0; res[which][1] = h1; res[which][2] = h2;
        #undef DO8
        #undef STEP
    }
    __syncthreads();

    if (tid == 0) {
        // Diagnostic for Round 2 (contraction test): deviation of truncated scans
        float d1 = fmaxf(fmaxf(fabsf(res[0][0]-res[1][0]), fabsf(res[0][1]-res[1][1])),
                         fabsf(res[0][2]-res[1][2]));
        float d2 = fmaxf(fmaxf(fabsf(res[0][0]-res[2][0]), fabsf(res[0][1]-res[2][1])),
                         fabsf(res[0][2]-res[2][2]));
        printf("TRUNCDIFF k4096=%.3e k256=%.3e\n", d1, d2);

        float h0 = fmaxf(res[0][0], 0.f);
        float h1 = fmaxf(res[0][1], 0.f);
        float h2 = fmaxf(res[0][2], 0.f);
        float z = fmaf(Wlin[0], h0, fmaf(Wlin[1], h1, fmaf(Wlin[2], h2, blin[0])));
        out[0] = 1.0f / (1.0f + expf(-z));
    }
}

extern "C" void kernel_launch(void* const* d_in, const int* in_sizes, int n_in,
                              void* d_out, int out_size) {
    const float* x    = (const float*)d_in[0];
    const int*   ei   = (const int*)  d_in[1];   // int32 (jax x64 disabled)
    const float* Wg   = (const float*)d_in[2];
    const float* bg   = (const float*)d_in[3];
    const float* Wih  = (const float*)d_in[4];
    const float* Whh  = (const float*)d_in[5];
    const float* bih  = (const float*)d_in[6];
    const float* bhh  = (const float*)d_in[7];
    const float* Wlin = (const float*)d_in[8];
    const float* blin = (const float*)d_in[9];
    float* out = (float*)d_out;

    k_init<<<(TN + 255)/256, 256>>>(x, Wg);
    k_deg <<<(TE + 255)/256, 256>>>(ei);
    k_msg <<<(TE + 255)/256, 256>>>(ei);
    k_node<<<(TN + 255)/256, 256>>>(bg, Wih, bih, bhh);
    k_scan<<<1, 96>>>(Whh, Wlin, blin, out);
}

// round 2
// speedup vs baseline: 18.6095x; 18.6095x over previous
#include <cuda_runtime.h>
#include <cstdio>
#include <math.h>

#define T 8
#define N 20000
#define E 1280000
#define TN (T*N)
#define TE (T*E)

#define CHUNKS 320
#define CLEN   500      // CHUNKS*CLEN == TN ; CLEN % 4 == 0
#define WARM   2048     // warmup steps (multiple of 4)

// Scratch (no allocations allowed -> __device__ globals)
__device__ float d_xl[TN*2];    // x @ W_gcn^T
__device__ float d_acc[TN*2];   // scatter accumulator
__device__ int   d_cnt[TN];     // edge-count per dst (deg = cnt+1 with self loop)
__device__ float d_u0[TN];      // SoA: W_ih*(gcn_out) + b_ih + b_hh
__device__ float d_u1[TN];
__device__ float d_u2[TN];
__device__ float d_s[CHUNKS][3];  // warmup-estimated state at chunk start
__device__ float d_b[CHUNKS][3];  // state at chunk end

// ---------------- init: zero accumulators, precompute xl ----------------
__global__ void k_init(const float* __restrict__ x, const float* __restrict__ Wg) {
    int g = blockIdx.x * blockDim.x + threadIdx.x;
    if (g >= TN) return;
    float w00 = Wg[0], w01 = Wg[1], w10 = Wg[2], w11 = Wg[3];
    float x0 = x[2*g], x1 = x[2*g+1];
    d_xl[2*g]   = fmaf(x0, w00, x1*w01);
    d_xl[2*g+1] = fmaf(x0, w10, x1*w11);
    d_acc[2*g] = 0.f; d_acc[2*g+1] = 0.f;
    d_cnt[g] = 0;
}

// ---------------- degree: count edges per dst ----------------
__global__ void k_deg(const int* __restrict__ ei) {
    int idx = blockIdx.x * blockDim.x + threadIdx.x;
    if (idx >= TE) return;
    int t = idx / E, e = idx - t*E;
    int dst = ei[(size_t)t*2*E + E + e];
    atomicAdd(&d_cnt[t*N + dst], 1);
}

// ---------------- messages: norm * xl[src] scattered to dst ----------------
__global__ void k_msg(const int* __restrict__ ei) {
    int idx = blockIdx.x * blockDim.x + threadIdx.x;
    if (idx >= TE) return;
    int t = idx / E, e = idx - t*E;
    const int* eit = ei + (size_t)t*2*E;
    int src = eit[e], dst = eit[E + e];
    int base = t*N;
    float di = rsqrtf((float)(d_cnt[base + src] + 1));
    float dj = rsqrtf((float)(d_cnt[base + dst] + 1));
    float nrm = di * dj;
    float m0 = d_xl[2*(base+src)], m1 = d_xl[2*(base+src)+1];
    atomicAdd(&d_acc[2*(base+dst)],     nrm*m0);
    atomicAdd(&d_acc[2*(base+dst)+1],   nrm*m1);
}

// ---------------- per-node epilogue: self-loop + bias, project to u (SoA) ----------------
__global__ void k_node(const float* __restrict__ bg, const float* __restrict__ Wih,
                       const float* __restrict__ bih, const float* __restrict__ bhh) {
    int g = blockIdx.x * blockDim.x + threadIdx.x;
    if (g >= TN) return;
    float inv = 1.0f / (float)(d_cnt[g] + 1);   // dinv^2 for self loop
    float g0 = d_acc[2*g]   + inv * d_xl[2*g]   + bg[0];
    float g1 = d_acc[2*g+1] + inv * d_xl[2*g+1] + bg[1];
    d_u0[g] = fmaf(Wih[0], g0, fmaf(Wih[1], g1, bih[0] + bhh[0]));
    d_u1[g] = fmaf(Wih[2], g0, fmaf(Wih[3], g1, bih[1] + bhh[1]));
    d_u2[g] = fmaf(Wih[4], g0, fmaf(Wih[5], g1, bih[2] + bhh[2]));
}

// ---------------- scan helpers ----------------
__device__ __forceinline__ float tanh_fast(float x) {
    float e = __expf(2.0f * x);                 // MUFU.EX2 path
    return 1.0f - __fdividef(2.0f, e + 1.0f);   // MUFU.RCP path
}

#define STEPM(c0, c1, c2) { \
    float a0 = fmaf(w00,h0, fmaf(w01,h1, fmaf(w02,h2, (c0)))); \
    float a1 = fmaf(w10,h0, fmaf(w11,h1, fmaf(w12,h2, (c1)))); \
    float a2 = fmaf(w20,h0, fmaf(w21,h1, fmaf(w22,h2, (c2)))); \
    h0 = tanh_fast(a0); h1 = tanh_fast(a1); h2 = tanh_fast(a2); }

// ---------------- parallel chunk scan with warmup ----------------
__global__ void k_pscan(const float* __restrict__ Whh) {
    int c = blockIdx.x * blockDim.x + threadIdx.x;
    if (c >= CHUNKS) return;
    float w00=Whh[0], w01=Whh[1], w02=Whh[2];
    float w10=Whh[3], w11=Whh[4], w12=Whh[5];
    float w20=Whh[6], w21=Whh[7], w22=Whh[8];

    int k0  = c * CLEN;
    int end = k0 + CLEN;
    int ws  = k0 - WARM; if (ws < 0) ws = 0;   // all starts multiple of 4

    float h0 = 0.f, h1 = 0.f, h2 = 0.f;
    for (int k = ws; k < end; k += 4) {
        if (k == k0) { d_s[c][0]=h0; d_s[c][1]=h1; d_s[c][2]=h2; }
        float4 a = *reinterpret_cast<const float4*>(d_u0 + k);
        float4 b = *reinterpret_cast<const float4*>(d_u1 + k);
        float4 u = *reinterpret_cast<const float4*>(d_u2 + k);
        STEPM(a.x, b.x, u.x);
        STEPM(a.y, b.y, u.y);
        STEPM(a.z, b.z, u.z);
        STEPM(a.w, b.w, u.w);
    }
    d_b[c][0]=h0; d_b[c][1]=h1; d_b[c][2]=h2;
}

// ---------------- verify + finish (exact serial fallback if not contracting) ----------------
__global__ void k_finish(const float* __restrict__ Whh, const float* __restrict__ Wlin,
                         const float* __restrict__ blin, float* __restrict__ out) {
    float w00=Whh[0], w01=Whh[1], w02=Whh[2];
    float w10=Whh[3], w11=Whh[4], w12=Whh[5];
    float w20=Whh[6], w21=Whh[7], w22=Whh[8];

    float md = 0.f;
    for (int c = 1; c < CHUNKS; c++) {
        md = fmaxf(md, fabsf(d_s[c][0] - d_b[c-1][0]));
        md = fmaxf(md, fabsf(d_s[c][1] - d_b[c-1][1]));
        md = fmaxf(md, fabsf(d_s[c][2] - d_b[c-1][2]));
    }
    printf("CHUNKDIFF max=%.3e\n", md);   // diagnostic (data only)

    float h0, h1, h2;
    if (md < 2e-5f) {
        // converged: chunk results are initial-condition independent -> exact
        h0 = d_b[CHUNKS-1][0]; h1 = d_b[CHUNKS-1][1]; h2 = d_b[CHUNKS-1][2];
    } else {
        // fallback: exact full serial scan
        h0 = 0.f; h1 = 0.f; h2 = 0.f;
        for (int k = 0; k < TN; k += 4) {
            float4 a = *reinterpret_cast<const float4*>(d_u0 + k);
            float4 b = *reinterpret_cast<const float4*>(d_u1 + k);
            float4 u = *reinterpret_cast<const float4*>(d_u2 + k);
            STEPM(a.x, b.x, u.x);
            STEPM(a.y, b.y, u.y);
            STEPM(a.z, b.z, u.z);
            STEPM(a.w, b.w, u.w);
        }
    }

    h0 = fmaxf(h0, 0.f); h1 = fmaxf(h1, 0.f); h2 = fmaxf(h2, 0.f);
    float z = fmaf(Wlin[0], h0, fmaf(Wlin[1], h1, fmaf(Wlin[2], h2, blin[0])));
    out[0] = 1.0f / (1.0f + expf(-z));
}

extern "C" void kernel_launch(void* const* d_in, const int* in_sizes, int n_in,
                              void* d_out, int out_size) {
    const float* x    = (const float*)d_in[0];
    const int*   ei   = (const int*)  d_in[1];   // int32
    const float* Wg   = (const float*)d_in[2];
    const float* bg   = (const float*)d_in[3];
    const float* Wih  = (const float*)d_in[4];
    const float* Whh  = (const float*)d_in[5];
    const float* bih  = (const float*)d_in[6];
    const float* bhh  = (const float*)d_in[7];
    const float* Wlin = (const float*)d_in[8];
    const float* blin = (const float*)d_in[9];
    float* out = (float*)d_out;

    k_init<<<(TN + 255)/256, 256>>>(x, Wg);
    k_deg <<<(TE + 255)/256, 256>>>(ei);
    k_msg <<<(TE + 255)/256, 256>>>(ei);
    k_node<<<(TN + 255)/256, 256>>>(bg, Wih, bih, bhh);
    k_pscan<<<(CHUNKS + 31)/32, 32>>>(Whh);
    k_finish<<<1, 1>>>(Whh, Wlin, blin, out);
}

// round 3
// speedup vs baseline: 38.7705x; 2.0834x over previous
#include <cuda_runtime.h>
#include <cstdio>
#include <math.h>

#define T 8
#define N 20000
#define E 1280000
#define TN (T*N)
#define TE (T*E)

#define CHUNKS 1600
#define CLEN   100      // CHUNKS*CLEN == TN ; CLEN % 4 == 0
#define WARM   768      // warmup steps (multiple of 4)

// Scratch (no allocations allowed -> __device__ globals)
__device__ float  d_xl[TN*2];    // x @ W_gcn^T (interleaved)
__device__ float  d_acc[TN*2];   // scatter accumulator (interleaved, float2-aligned)
__device__ int    d_cnt[TN];     // edge-count per dst (deg = cnt+1 with self loop)
__device__ float  d_dinv[TN];    // deg^-1/2
__device__ float2 d_p[TN];       // dinv * xl  (premultiplied message)
__device__ float  d_u0[TN];      // SoA RNN input
__device__ float  d_u1[TN];
__device__ float  d_u2[TN];
__device__ float  d_s[CHUNKS][3];  // warmup-estimated state at chunk start
__device__ float  d_b[CHUNKS][3];  // state at chunk end

// ---------------- init: zero accumulators, precompute xl ----------------
__global__ void k_init(const float* __restrict__ x, const float* __restrict__ Wg) {
    int g = blockIdx.x * blockDim.x + threadIdx.x;
    if (g >= TN) return;
    float w00 = Wg[0], w01 = Wg[1], w10 = Wg[2], w11 = Wg[3];
    float x0 = x[2*g], x1 = x[2*g+1];
    d_xl[2*g]   = fmaf(x0, w00, x1*w01);
    d_xl[2*g+1] = fmaf(x0, w10, x1*w11);
    d_acc[2*g] = 0.f; d_acc[2*g+1] = 0.f;
    d_cnt[g] = 0;
}

// ---------------- degree: count edges per dst (4 edges/thread) ----------------
__global__ void k_deg(const int* __restrict__ ei) {
    int idx = blockIdx.x * blockDim.x + threadIdx.x;
    if (idx >= TE/4) return;
    int t = idx / (E/4), e4 = idx - t*(E/4);
    int4 d4 = *reinterpret_cast<const int4*>(ei + (size_t)t*2*E + E + 4*e4);
    int base = t*N;
    atomicAdd(&d_cnt[base + d4.x], 1);
    atomicAdd(&d_cnt[base + d4.y], 1);
    atomicAdd(&d_cnt[base + d4.z], 1);
    atomicAdd(&d_cnt[base + d4.w], 1);
}

// ---------------- prep: dinv and premultiplied messages ----------------
__global__ void k_prep() {
    int g = blockIdx.x * blockDim.x + threadIdx.x;
    if (g >= TN) return;
    float dinv = rsqrtf((float)(d_cnt[g] + 1));
    d_dinv[g] = dinv;
    d_p[g] = make_float2(dinv * d_xl[2*g], dinv * d_xl[2*g+1]);
}

// ---------------- messages: acc[dst] += p[src]  (4 edges/thread, v2 RED) ----------------
__device__ __forceinline__ void red2(float* ptr, float2 v) {
    asm volatile("red.global.add.v2.f32 [%0], {%1, %2};"
                 :: "l"(ptr), "f"(v.x), "f"(v.y) : "memory");
}

__global__ void k_msg(const int* __restrict__ ei) {
    int idx = blockIdx.x * blockDim.x + threadIdx.x;
    if (idx >= TE/4) return;
    int t = idx / (E/4), e4 = idx - t*(E/4);
    const int* eit = ei + (size_t)t*2*E;
    int4 s4 = *reinterpret_cast<const int4*>(eit + 4*e4);
    int4 t4 = *reinterpret_cast<const int4*>(eit + E + 4*e4);
    int base = t*N;
    red2(d_acc + 2*(base + t4.x), d_p[base + s4.x]);
    red2(d_acc + 2*(base + t4.y), d_p[base + s4.y]);
    red2(d_acc + 2*(base + t4.z), d_p[base + s4.z]);
    red2(d_acc + 2*(base + t4.w), d_p[base + s4.w]);
}

// ---------------- per-node epilogue: scale by dinv[dst], self-loop, project to u ----------------
__global__ void k_node(const float* __restrict__ bg, const float* __restrict__ Wih,
                       const float* __restrict__ bih, const float* __restrict__ bhh) {
    int g = blockIdx.x * blockDim.x + threadIdx.x;
    if (g >= TN) return;
    float dinv = d_dinv[g];
    float inv = dinv * dinv;                    // 1/deg for self loop
    float g0 = fmaf(dinv, d_acc[2*g],   fmaf(inv, d_xl[2*g],   bg[0]));
    float g1 = fmaf(dinv, d_acc[2*g+1], fmaf(inv, d_xl[2*g+1], bg[1]));
    d_u0[g] = fmaf(Wih[0], g0, fmaf(Wih[1], g1, bih[0] + bhh[0]));
    d_u1[g] = fmaf(Wih[2], g0, fmaf(Wih[3], g1, bih[1] + bhh[1]));
    d_u2[g] = fmaf(Wih[4], g0, fmaf(Wih[5], g1, bih[2] + bhh[2]));
}

// ---------------- scan helpers ----------------
__device__ __forceinline__ float tanh_fast(float x) {
    float e = __expf(2.0f * x);                 // MUFU.EX2 path
    return 1.0f - __fdividef(2.0f, e + 1.0f);   // MUFU.RCP path
}

#define STEPM(c0, c1, c2) { \
    float a0 = fmaf(w00,h0, fmaf(w01,h1, fmaf(w02,h2, (c0)))); \
    float a1 = fmaf(w10,h0, fmaf(w11,h1, fmaf(w12,h2, (c1)))); \
    float a2 = fmaf(w20,h0, fmaf(w21,h1, fmaf(w22,h2, (c2)))); \
    h0 = tanh_fast(a0); h1 = tanh_fast(a1); h2 = tanh_fast(a2); }

#define QUAD(k) { \
    float4 a = *reinterpret_cast<const float4*>(d_u0 + (k)); \
    float4 b = *reinterpret_cast<const float4*>(d_u1 + (k)); \
    float4 u = *reinterpret_cast<const float4*>(d_u2 + (k)); \
    STEPM(a.x, b.x, u.x); \
    STEPM(a.y, b.y, u.y); \
    STEPM(a.z, b.z, u.z); \
    STEPM(a.w, b.w, u.w); }

// ---------------- parallel chunk scan with warmup ----------------
__global__ void k_pscan(const float* __restrict__ Whh) {
    int c = blockIdx.x * blockDim.x + threadIdx.x;
    if (c >= CHUNKS) return;
    float w00=Whh[0], w01=Whh[1], w02=Whh[2];
    float w10=Whh[3], w11=Whh[4], w12=Whh[5];
    float w20=Whh[6], w21=Whh[7], w22=Whh[8];

    int k0  = c * CLEN;
    int ws  = k0 - WARM; if (ws < 0) ws = 0;   // all multiples of 4

    float h0 = 0.f, h1 = 0.f, h2 = 0.f;
    for (int k = ws; k < k0; k += 4) QUAD(k);
    d_s[c][0]=h0; d_s[c][1]=h1; d_s[c][2]=h2;
    #pragma unroll 5
    for (int k = k0; k < k0 + CLEN; k += 4) QUAD(k);
    d_b[c][0]=h0; d_b[c][1]=h1; d_b[c][2]=h2;
}

// ---------------- verify + finish (exact serial fallback if not converged) ----------------
__global__ void k_finish(const float* __restrict__ Whh, const float* __restrict__ Wlin,
                         const float* __restrict__ blin, float* __restrict__ out) {
    __shared__ float smax[8];
    int tid = threadIdx.x;

    float lmax = 0.f;
    for (int c = 1 + tid; c < CHUNKS; c += blockDim.x) {
        lmax = fmaxf(lmax, fabsf(d_s[c][0] - d_b[c-1][0]));
        lmax = fmaxf(lmax, fabsf(d_s[c][1] - d_b[c-1][1]));
        lmax = fmaxf(lmax, fabsf(d_s[c][2] - d_b[c-1][2]));
    }
    #pragma unroll
    for (int o = 16; o; o >>= 1)
        lmax = fmaxf(lmax, __shfl_xor_sync(0xffffffff, lmax, o));
    if ((tid & 31) == 0) smax[tid >> 5] = lmax;
    __syncthreads();

    if (tid == 0) {
        float md = 0.f;
        for (int i = 0; i < (int)(blockDim.x + 31)/32; i++) md = fmaxf(md, smax[i]);
        printf("CHUNKDIFF max=%.3e\n", md);   // diagnostic (data only)

        float w00=Whh[0], w01=Whh[1], w02=Whh[2];
        float w10=Whh[3], w11=Whh[4], w12=Whh[5];
        float w20=Whh[6], w21=Whh[7], w22=Whh[8];
        float h0, h1, h2;
        if (md < 2e-5f) {
            h0 = d_b[CHUNKS-1][0]; h1 = d_b[CHUNKS-1][1]; h2 = d_b[CHUNKS-1][2];
        } else {
            // fallback: exact full serial scan
            h0 = 0.f; h1 = 0.f; h2 = 0.f;
            for (int k = 0; k < TN; k += 4) QUAD(k);
        }
        h0 = fmaxf(h0, 0.f); h1 = fmaxf(h1, 0.f); h2 = fmaxf(h2, 0.f);
        float z = fmaf(Wlin[0], h0, fmaf(Wlin[1], h1, fmaf(Wlin[2], h2, blin[0])));
        out[0] = 1.0f / (1.0f + expf(-z));
    }
}

extern "C" void kernel_launch(void* const* d_in, const int* in_sizes, int n_in,
                              void* d_out, int out_size) {
    const float* x    = (const float*)d_in[0];
    const int*   ei   = (const int*)  d_in[1];   // int32
    const float* Wg   = (const float*)d_in[2];
    const float* bg   = (const float*)d_in[3];
    const float* Wih  = (const float*)d_in[4];
    const float* Whh  = (const float*)d_in[5];
    const float* bih  = (const float*)d_in[6];
    const float* bhh  = (const float*)d_in[7];
    const float* Wlin = (const float*)d_in[8];
    const float* blin = (const float*)d_in[9];
    float* out = (float*)d_out;

    k_init<<<(TN + 255)/256, 256>>>(x, Wg);
    k_deg <<<(TE/4 + 255)/256, 256>>>(ei);
    k_prep<<<(TN + 255)/256, 256>>>();
    k_msg <<<(TE/4 + 255)/256, 256>>>(ei);
    k_node<<<(TN + 255)/256, 256>>>(bg, Wih, bih, bhh);
    k_pscan<<<(CHUNKS + 127)/128, 128>>>(Whh);
    k_finish<<<1, 256>>>(Whh, Wlin, blin, out);
}

// round 4
// speedup vs baseline: 43.4953x; 1.1219x over previous
#include <cuda_runtime.h>
#include <math.h>

#define T 8
#define N 20000
#define E 1280000
#define TN (T*N)
#define TE (T*E)

#define CHUNKS 1600
#define CLEN   100      // CHUNKS*CLEN == TN ; CLEN % 4 == 0
#define WARM   768      // warmup steps (multiple of 4)

#define INIT_BLOCKS ((TN + 255) / 256)
#define DEG_BLOCKS  ((TE/8 + 255) / 256)

// Scratch (no allocations -> __device__ globals). Zero-initialized at load;
// every launch leaves d_cnt and d_acc zeroed again (self-cleaning).
__device__ float  d_xl[TN*2];    // x @ W_gcn^T (interleaved)
__device__ float  d_acc[TN*2];   // scatter accumulator (zeroed by k_node after use)
__device__ int    d_cnt[TN];     // edge-count per dst (zeroed by k_prep after use)
__device__ float  d_dinv[TN];    // deg^-1/2
__device__ float2 d_p[TN];       // dinv * xl  (premultiplied message)
__device__ float  d_u0[TN];      // SoA RNN input
__device__ float  d_u1[TN];
__device__ float  d_u2[TN];
__device__ float  d_s[CHUNKS][3];  // warmup-estimated state at chunk start
__device__ float  d_b[CHUNKS][3];  // state at chunk end

// ---------------- fused: xl precompute (init blocks) + degree histogram ----------------
__global__ void k_initdeg(const float* __restrict__ x, const float* __restrict__ Wg,
                          const int* __restrict__ ei) {
    int b = blockIdx.x;
    if (b < INIT_BLOCKS) {
        int g = b * 256 + threadIdx.x;
        if (g >= TN) return;
        float w00 = Wg[0], w01 = Wg[1], w10 = Wg[2], w11 = Wg[3];
        float x0 = x[2*g], x1 = x[2*g+1];
        d_xl[2*g]   = fmaf(x0, w00, x1*w01);
        d_xl[2*g+1] = fmaf(x0, w10, x1*w11);
    } else {
        int idx = (b - INIT_BLOCKS) * 256 + threadIdx.x;   // < TE/8 exactly
        if (idx >= TE/8) return;
        int t = idx / (E/8), e8 = idx - t*(E/8);
        const int* dp = ei + (size_t)t*2*E + E + 8*e8;
        int4 a = *reinterpret_cast<const int4*>(dp);
        int4 c = *reinterpret_cast<const int4*>(dp + 4);
        int base = t*N;
        atomicAdd(&d_cnt[base + a.x], 1);
        atomicAdd(&d_cnt[base + a.y], 1);
        atomicAdd(&d_cnt[base + a.z], 1);
        atomicAdd(&d_cnt[base + a.w], 1);
        atomicAdd(&d_cnt[base + c.x], 1);
        atomicAdd(&d_cnt[base + c.y], 1);
        atomicAdd(&d_cnt[base + c.z], 1);
        atomicAdd(&d_cnt[base + c.w], 1);
    }
}

// ---------------- prep: dinv and premultiplied messages; re-zero d_cnt ----------------
__global__ void k_prep() {
    int g = blockIdx.x * blockDim.x + threadIdx.x;
    if (g >= TN) return;
    int cnt = d_cnt[g];
    d_cnt[g] = 0;                                  // self-clean for next launch
    float dinv = rsqrtf((float)(cnt + 1));
    d_dinv[g] = dinv;
    d_p[g] = make_float2(dinv * d_xl[2*g], dinv * d_xl[2*g+1]);
}

// ---------------- messages: acc[dst] += p[src]  (8 edges/thread, batched gathers) ----------------
__device__ __forceinline__ void red2(float* ptr, float2 v) {
    asm volatile("red.global.add.v2.f32 [%0], {%1, %2};"
                 :: "l"(ptr), "f"(v.x), "f"(v.y) : "memory");
}

__global__ void k_msg(const int* __restrict__ ei) {
    int idx = blockIdx.x * blockDim.x + threadIdx.x;
    if (idx >= TE/8) return;
    int t = idx / (E/8), e8 = idx - t*(E/8);
    const int* eit = ei + (size_t)t*2*E;
    int4 s0 = *reinterpret_cast<const int4*>(eit + 8*e8);
    int4 s1 = *reinterpret_cast<const int4*>(eit + 8*e8 + 4);
    int4 t0 = *reinterpret_cast<const int4*>(eit + E + 8*e8);
    int4 t1 = *reinterpret_cast<const int4*>(eit + E + 8*e8 + 4);
    int base = t*N;
    // all gathers issued before any RED (REDs carry memory clobbers and
    // would otherwise serialize against later loads)
    float2 p0 = d_p[base + s0.x];
    float2 p1 = d_p[base + s0.y];
    float2 p2 = d_p[base + s0.z];
    float2 p3 = d_p[base + s0.w];
    float2 p4 = d_p[base + s1.x];
    float2 p5 = d_p[base + s1.y];
    float2 p6 = d_p[base + s1.z];
    float2 p7 = d_p[base + s1.w];
    red2(d_acc + 2*(base + t0.x), p0);
    red2(d_acc + 2*(base + t0.y), p1);
    red2(d_acc + 2*(base + t0.z), p2);
    red2(d_acc + 2*(base + t0.w), p3);
    red2(d_acc + 2*(base + t1.x), p4);
    red2(d_acc + 2*(base + t1.y), p5);
    red2(d_acc + 2*(base + t1.z), p6);
    red2(d_acc + 2*(base + t1.w), p7);
}

// ---------------- per-node epilogue: scale, self-loop, project to u; re-zero d_acc ----------------
__global__ void k_node(const float* __restrict__ bg, const float* __restrict__ Wih,
                       const float* __restrict__ bih, const float* __restrict__ bhh) {
    int g = blockIdx.x * blockDim.x + threadIdx.x;
    if (g >= TN) return;
    float dinv = d_dinv[g];
    float inv = dinv * dinv;                    // 1/deg for self loop
    float a0 = d_acc[2*g], a1 = d_acc[2*g+1];
    d_acc[2*g] = 0.f; d_acc[2*g+1] = 0.f;       // self-clean for next launch
    float g0 = fmaf(dinv, a0, fmaf(inv, d_xl[2*g],   bg[0]));
    float g1 = fmaf(dinv, a1, fmaf(inv, d_xl[2*g+1], bg[1]));
    d_u0[g] = fmaf(Wih[0], g0, fmaf(Wih[1], g1, bih[0] + bhh[0]));
    d_u1[g] = fmaf(Wih[2], g0, fmaf(Wih[3], g1, bih[1] + bhh[1]));
    d_u2[g] = fmaf(Wih[4], g0, fmaf(Wih[5], g1, bih[2] + bhh[2]));
}

// ---------------- scan helpers ----------------
__device__ __forceinline__ float tanh_fast(float x) {
    float e = __expf(2.0f * x);                 // MUFU.EX2 path
    return 1.0f - __fdividef(2.0f, e + 1.0f);   // MUFU.RCP path
}

#define STEPM(c0, c1, c2) { \
    float a0 = fmaf(w00,h0, fmaf(w01,h1, fmaf(w02,h2, (c0)))); \
    float a1 = fmaf(w10,h0, fmaf(w11,h1, fmaf(w12,h2, (c1)))); \
    float a2 = fmaf(w20,h0, fmaf(w21,h1, fmaf(w22,h2, (c2)))); \
    h0 = tanh_fast(a0); h1 = tanh_fast(a1); h2 = tanh_fast(a2); }

#define QUAD(k) { \
    float4 a = *reinterpret_cast<const float4*>(d_u0 + (k)); \
    float4 b = *reinterpret_cast<const float4*>(d_u1 + (k)); \
    float4 u = *reinterpret_cast<const float4*>(d_u2 + (k)); \
    STEPM(a.x, b.x, u.x); \
    STEPM(a.y, b.y, u.y); \
    STEPM(a.z, b.z, u.z); \
    STEPM(a.w, b.w, u.w); }

// ---------------- parallel chunk scan with warmup ----------------
__global__ void k_pscan(const float* __restrict__ Whh) {
    int c = blockIdx.x * blockDim.x + threadIdx.x;
    if (c >= CHUNKS) return;
    float w00=Whh[0], w01=Whh[1], w02=Whh[2];
    float w10=Whh[3], w11=Whh[4], w12=Whh[5];
    float w20=Whh[6], w21=Whh[7], w22=Whh[8];

    int k0  = c * CLEN;
    int ws  = k0 - WARM; if (ws < 0) ws = 0;   // all multiples of 4

    float h0 = 0.f, h1 = 0.f, h2 = 0.f;
    for (int k = ws; k < k0; k += 4) QUAD(k);
    d_s[c][0]=h0; d_s[c][1]=h1; d_s[c][2]=h2;
    #pragma unroll 5
    for (int k = k0; k < k0 + CLEN; k += 4) QUAD(k);
    d_b[c][0]=h0; d_b[c][1]=h1; d_b[c][2]=h2;
}

// ---------------- verify + finish (exact serial fallback if not converged) ----------------
__global__ void k_finish(const float* __restrict__ Whh, const float* __restrict__ Wlin,
                         const float* __restrict__ blin, float* __restrict__ out) {
    __shared__ float smax[8];
    int tid = threadIdx.x;

    float lmax = 0.f;
    for (int c = 1 + tid; c < CHUNKS; c += blockDim.x) {
        lmax = fmaxf(lmax, fabsf(d_s[c][0] - d_b[c-1][0]));
        lmax = fmaxf(lmax, fabsf(d_s[c][1] - d_b[c-1][1]));
        lmax = fmaxf(lmax, fabsf(d_s[c][2] - d_b[c-1][2]));
    }
    #pragma unroll
    for (int o = 16; o; o >>= 1)
        lmax = fmaxf(lmax, __shfl_xor_sync(0xffffffff, lmax, o));
    if ((tid & 31) == 0) smax[tid >> 5] = lmax;
    __syncthreads();

    if (tid == 0) {
        float md = 0.f;
        for (int i = 0; i < (int)(blockDim.x + 31)/32; i++) md = fmaxf(md, smax[i]);

        float w00=Whh[0], w01=Whh[1], w02=Whh[2];
        float w10=Whh[3], w11=Whh[4], w12=Whh[5];
        float w20=Whh[6], w21=Whh[7], w22=Whh[8];
        float h0, h1, h2;
        if (md < 2e-5f) {
            h0 = d_b[CHUNKS-1][0]; h1 = d_b[CHUNKS-1][1]; h2 = d_b[CHUNKS-1][2];
        } else {
            // fallback: exact full serial scan
            h0 = 0.f; h1 = 0.f; h2 = 0.f;
            for (int k = 0; k < TN; k += 4) QUAD(k);
        }
        h0 = fmaxf(h0, 0.f); h1 = fmaxf(h1, 0.f); h2 = fmaxf(h2, 0.f);
        float z = fmaf(Wlin[0], h0, fmaf(Wlin[1], h1, fmaf(Wlin[2], h2, blin[0])));
        out[0] = 1.0f / (1.0f + expf(-z));
    }
}

extern "C" void kernel_launch(void* const* d_in, const int* in_sizes, int n_in,
                              void* d_out, int out_size) {
    const float* x    = (const float*)d_in[0];
    const int*   ei   = (const int*)  d_in[1];   // int32
    const float* Wg   = (const float*)d_in[2];
    const float* bg   = (const float*)d_in[3];
    const float* Wih  = (const float*)d_in[4];
    const float* Whh  = (const float*)d_in[5];
    const float* bih  = (const float*)d_in[6];
    const float* bhh  = (const float*)d_in[7];
    const float* Wlin = (const float*)d_in[8];
    const float* blin = (const float*)d_in[9];
    float* out = (float*)d_out;

    k_initdeg<<<INIT_BLOCKS + DEG_BLOCKS, 256>>>(x, Wg, ei);
    k_prep<<<(TN + 255)/256, 256>>>();
    k_msg <<<(TE/8 + 255)/256, 256>>>(ei);
    k_node<<<(TN + 255)/256, 256>>>(bg, Wih, bih, bhh);
    k_pscan<<<(CHUNKS + 127)/128, 128>>>(Whh);
    k_finish<<<1, 256>>>(Whh, Wlin, blin, out);
}

// round 5
// speedup vs baseline: 117.6972x; 2.7060x over previous
#include <cuda_runtime.h>
#include <math.h>

#define T 8
#define N 20000
#define E 1280000
#define TN (T*N)

#define TAIL   2560
#define CHUNKS 32
#define CLEN   80          // CHUNKS*CLEN == TAIL
#define WARM   640         // warmup steps (multiple of 4)
#define KEEP   (TAIL + WARM)   // 3200 tail nodes of graph 7 need u
#define NODE0  (N - KEEP)      // first needed node of graph 7

#define XL_BLOCKS  ((N + 255) / 256)   // 79
#define DEG_BLOCKS (E/8/256)           // 625 (exact)

// ---- cheap-path scratch (graph 7 only); self-cleaning across graph replays ----
__device__ float  d_xl[N*2];      // xl for graph-7 nodes
__device__ int    d_cnt[N];       // degree counts (zeroed by k_prep7 after use)
__device__ float  d_dinv[N];
__device__ float2 d_p[N];         // dinv * xl
__device__ float  d_acc[KEEP*2];  // tail-local accumulator (zeroed by k_node7)
__device__ float  d_u0[KEEP], d_u1[KEEP], d_u2[KEEP];

// ---- fallback scratch (full problem; zeroed at fallback start) ----
__device__ int    f_cnt[TN];
__device__ float2 f_p[TN];
__device__ float  f_acc[TN*2];
__device__ float  f_u[TN*3];

// ---------------- graph-7 xl + degree histogram (fused) ----------------
__global__ void k_deg7(const float* __restrict__ x, const float* __restrict__ Wg,
                       const int* __restrict__ ei) {
    int b = blockIdx.x;
    if (b < XL_BLOCKS) {
        int n = b * 256 + threadIdx.x;
        if (n >= N) return;
        float x0 = x[2*(7*N + n)], x1 = x[2*(7*N + n) + 1];
        d_xl[2*n]   = fmaf(x0, Wg[0], x1 * Wg[1]);
        d_xl[2*n+1] = fmaf(x0, Wg[2], x1 * Wg[3]);
    } else {
        int idx = (b - XL_BLOCKS) * 256 + threadIdx.x;   // < E/8 exactly
        const int* dp = ei + (size_t)7*2*E + E + 8*idx;
        int4 a = *reinterpret_cast<const int4*>(dp);
        int4 c = *reinterpret_cast<const int4*>(dp + 4);
        atomicAdd(&d_cnt[a.x], 1); atomicAdd(&d_cnt[a.y], 1);
        atomicAdd(&d_cnt[a.z], 1); atomicAdd(&d_cnt[a.w], 1);
        atomicAdd(&d_cnt[c.x], 1); atomicAdd(&d_cnt[c.y], 1);
        atomicAdd(&d_cnt[c.z], 1); atomicAdd(&d_cnt[c.w], 1);
    }
}

// ---------------- dinv + premultiplied messages; re-zero d_cnt ----------------
__global__ void k_prep7() {
    int n = blockIdx.x * blockDim.x + threadIdx.x;
    if (n >= N) return;
    int cnt = d_cnt[n];
    d_cnt[n] = 0;                                   // self-clean
    float dinv = rsqrtf((float)(cnt + 1));
    d_dinv[n] = dinv;
    d_p[n] = make_float2(dinv * d_xl[2*n], dinv * d_xl[2*n+1]);
}

// ---------------- messages into the tail only ----------------
__device__ __forceinline__ void red2(float* ptr, float2 v) {
    asm volatile("red.global.add.v2.f32 [%0], {%1, %2};"
                 :: "l"(ptr), "f"(v.x), "f"(v.y) : "memory");
}

__global__ void k_msg7(const int* __restrict__ ei) {
    int idx = blockIdx.x * blockDim.x + threadIdx.x;    // < E/8 exactly
    const int* eit = ei + (size_t)7*2*E;
    int4 s0 = *reinterpret_cast<const int4*>(eit + 8*idx);
    int4 s1 = *reinterpret_cast<const int4*>(eit + 8*idx + 4);
    int4 t0 = *reinterpret_cast<const int4*>(eit + E + 8*idx);
    int4 t1 = *reinterpret_cast<const int4*>(eit + E + 8*idx + 4);
    #define EDGE(S, D) if ((D) >= NODE0) red2(d_acc + 2*((D) - NODE0), d_p[(S)]);
    EDGE(s0.x, t0.x) EDGE(s0.y, t0.y) EDGE(s0.z, t0.z) EDGE(s0.w, t0.w)
    EDGE(s1.x, t1.x) EDGE(s1.y, t1.y) EDGE(s1.z, t1.z) EDGE(s1.w, t1.w)
    #undef EDGE
}

// ---------------- tail node epilogue -> u; re-zero d_acc ----------------
// gcn = dinv*acc + dinv^2*xl + bg = dinv*(acc + p) + bg   (since p = dinv*xl)
__global__ void k_node7(const float* __restrict__ bg, const float* __restrict__ Wih,
                        const float* __restrict__ bih, const float* __restrict__ bhh) {
    int i = blockIdx.x * blockDim.x + threadIdx.x;
    if (i >= KEEP) return;
    int n = NODE0 + i;
    float dinv = d_dinv[n];
    float2 p = d_p[n];
    float a0 = d_acc[2*i], a1 = d_acc[2*i+1];
    d_acc[2*i] = 0.f; d_acc[2*i+1] = 0.f;            // self-clean
    float g0 = fmaf(dinv, a0 + p.x, bg[0]);
    float g1 = fmaf(dinv, a1 + p.y, bg[1]);
    d_u0[i] = fmaf(Wih[0], g0, fmaf(Wih[1], g1, bih[0] + bhh[0]));
    d_u1[i] = fmaf(Wih[2], g0, fmaf(Wih[3], g1, bih[1] + bhh[1]));
    d_u2[i] = fmaf(Wih[4], g0, fmaf(Wih[5], g1, bih[2] + bhh[2]));
}

// ---------------- scan helpers ----------------
__device__ __forceinline__ float tanh_fast(float x) {
    float e = __expf(2.0f * x);
    return 1.0f - __fdividef(2.0f, e + 1.0f);
}

#define STEPM(c0, c1, c2) { \
    float a0 = fmaf(w00,h0, fmaf(w01,h1, fmaf(w02,h2, (c0)))); \
    float a1 = fmaf(w10,h0, fmaf(w11,h1, fmaf(w12,h2, (c1)))); \
    float a2 = fmaf(w20,h0, fmaf(w21,h1, fmaf(w22,h2, (c2)))); \
    h0 = tanh_fast(a0); h1 = tanh_fast(a1); h2 = tanh_fast(a2); }

#define QUAD(k) { \
    float4 a = *reinterpret_cast<const float4*>(d_u0 + (k)); \
    float4 b = *reinterpret_cast<const float4*>(d_u1 + (k)); \
    float4 u = *reinterpret_cast<const float4*>(d_u2 + (k)); \
    STEPM(a.x, b.x, u.x); STEPM(a.y, b.y, u.y); \
    STEPM(a.z, b.z, u.z); STEPM(a.w, b.w, u.w); }

// ---------------- scan + gate + output (+ full fallback if gate fails) ----------------
__global__ void k_finish(const float* __restrict__ x, const int* __restrict__ ei,
                         const float* __restrict__ Wg, const float* __restrict__ bg,
                         const float* __restrict__ Wih, const float* __restrict__ Whh,
                         const float* __restrict__ bih, const float* __restrict__ bhh,
                         const float* __restrict__ Wlin, const float* __restrict__ blin,
                         float* __restrict__ out) {
    __shared__ float s_s[34][3], s_b[32][3];
    __shared__ int s_ok;
    int tid = threadIdx.x;

    float w00=Whh[0], w01=Whh[1], w02=Whh[2];
    float w10=Whh[3], w11=Whh[4], w12=Whh[5];
    float w20=Whh[6], w21=Whh[7], w22=Whh[8];

    // --- chunked tail scan: threads 0..31 = chunks; 32,33 = entrance variants ---
    if (tid < 34) {
        int c = (tid < 32) ? tid : 0;
        int k0 = WARM + c * CLEN;
        int ws = k0 - WARM;                           // = c*CLEN, multiple of 4
        float init = (tid == 32) ? 1.f : (tid == 33 ? -1.f : 0.f);
        float h0 = init, h1 = init, h2 = init;
        for (int k = ws; k < k0; k += 4) QUAD(k);
        s_s[tid][0] = h0; s_s[tid][1] = h1; s_s[tid][2] = h2;
        if (tid < 32) {
            #pragma unroll 5
            for (int k = k0; k < k0 + CLEN; k += 4) QUAD(k);
            s_b[tid][0] = h0; s_b[tid][1] = h1; s_b[tid][2] = h2;
        }
    }
    __syncthreads();

    if (tid == 0) {
        float md = 0.f;
        for (int c = 1; c < 32; c++)
            for (int m = 0; m < 3; m++)
                md = fmaxf(md, fabsf(s_s[c][m] - s_b[c-1][m]));
        for (int m = 0; m < 3; m++) {               // entrance insensitivity
            md = fmaxf(md, fabsf(s_s[32][m] - s_s[0][m]));
            md = fmaxf(md, fabsf(s_s[33][m] - s_s[0][m]));
        }
        s_ok = (md < 2e-5f);
        if (s_ok) {
            float h0 = fmaxf(s_b[31][0], 0.f);
            float h1 = fmaxf(s_b[31][1], 0.f);
            float h2 = fmaxf(s_b[31][2], 0.f);
            float z = fmaf(Wlin[0], h0, fmaf(Wlin[1], h1, fmaf(Wlin[2], h2, blin[0])));
            out[0] = 1.0f / (1.0f + expf(-z));
        }
    }
    __syncthreads();
    if (s_ok) return;

    // ================= FALLBACK: exact full computation (block-parallel GCN,
    // serial scan). Runs only if the contraction gate fails. =================
    int nt = blockDim.x;
    for (int g = tid; g < TN; g += nt) { f_cnt[g] = 0; f_acc[2*g] = 0.f; f_acc[2*g+1] = 0.f; }
    __syncthreads();
    for (long i = tid; i < (long)T*E; i += nt) {
        int t = (int)(i / E), e = (int)(i - (long)t*E);
        int dst = ei[(size_t)t*2*E + E + e];
        atomicAdd(&f_cnt[t*N + dst], 1);
    }
    __syncthreads();
    for (int g = tid; g < TN; g += nt) {
        float x0 = x[2*g], x1 = x[2*g+1];
        float xl0 = fmaf(x0, Wg[0], x1*Wg[1]);
        float xl1 = fmaf(x0, Wg[2], x1*Wg[3]);
        float dinv = rsqrtf((float)(f_cnt[g] + 1));
        f_p[g] = make_float2(dinv * xl0, dinv * xl1);
    }
    __syncthreads();
    for (long i = tid; i < (long)T*E; i += nt) {
        int t = (int)(i / E), e = (int)(i - (long)t*E);
        const int* eit = ei + (size_t)t*2*E;
        int src = eit[e], dst = eit[E + e];
        float2 p = f_p[t*N + src];
        atomicAdd(&f_acc[2*(t*N + dst)],   p.x);
        atomicAdd(&f_acc[2*(t*N + dst)+1], p.y);
    }
    __syncthreads();
    for (int g = tid; g < TN; g += nt) {
        float dinv = rsqrtf((float)(f_cnt[g] + 1));
        float2 p = f_p[g];
        float g0 = fmaf(dinv, f_acc[2*g]   + p.x, bg[0]);
        float g1 = fmaf(dinv, f_acc[2*g+1] + p.y, bg[1]);
        f_u[3*g]   = fmaf(Wih[0], g0, fmaf(Wih[1], g1, bih[0] + bhh[0]));
        f_u[3*g+1] = fmaf(Wih[2], g0, fmaf(Wih[3], g1, bih[1] + bhh[1]));
        f_u[3*g+2] = fmaf(Wih[4], g0, fmaf(Wih[5], g1, bih[2] + bhh[2]));
    }
    __syncthreads();
    for (int g = tid; g < TN; g += nt) { f_cnt[g] = 0; f_acc[2*g] = 0.f; f_acc[2*g+1] = 0.f; }
    __syncthreads();
    if (tid == 0) {
        float h0 = 0.f, h1 = 0.f, h2 = 0.f;
        for (int k = 0; k < TN; k++) STEPM(f_u[3*k], f_u[3*k+1], f_u[3*k+2]);
        h0 = fmaxf(h0, 0.f); h1 = fmaxf(h1, 0.f); h2 = fmaxf(h2, 0.f);
        float z = fmaf(Wlin[0], h0, fmaf(Wlin[1], h1, fmaf(Wlin[2], h2, blin[0])));
        out[0] = 1.0f / (1.0f + expf(-z));
    }
}

extern "C" void kernel_launch(void* const* d_in, const int* in_sizes, int n_in,
                              void* d_out, int out_size) {
    const float* x    = (const float*)d_in[0];
    const int*   ei   = (const int*)  d_in[1];   // int32
    const float* Wg   = (const float*)d_in[2];
    const float* bg   = (const float*)d_in[3];
    const float* Wih  = (const float*)d_in[4];
    const float* Whh  = (const float*)d_in[5];
    const float* bih  = (const float*)d_in[6];
    const float* bhh  = (const float*)d_in[7];
    const float* Wlin = (const float*)d_in[8];
    const float* blin = (const float*)d_in[9];
    float* out = (float*)d_out;

    k_deg7 <<<XL_BLOCKS + DEG_BLOCKS, 256>>>(x, Wg, ei);
    k_prep7<<<XL_BLOCKS, 256>>>();
    k_msg7 <<<DEG_BLOCKS, 256>>>(ei);
    k_node7<<<(KEEP + 255)/256, 256>>>(bg, Wih, bih, bhh);
    k_finish<<<1, 1024>>>(x, ei, Wg, bg, Wih, Whh, bih, bhh, Wlin, blin, out);
}

// round 6
// speedup vs baseline: 138.0084x; 1.1726x over previous
#include <cuda_runtime.h>
#include <math.h>

#define T 8
#define N 20000
#define E 1280000
#define TN (T*N)

#define TAIL   2560
#define CHUNKS 64
#define CLEN   40          // CHUNKS*CLEN == TAIL ; multiple of 4
#define WARM   640         // warmup steps (multiple of 4)
#define KEEP   (TAIL + WARM)   // 3200 tail nodes of graph 7 need u
#define NODE0  (N - KEEP)      // first needed node of graph 7

#define K_SCALE 2.8853900817779268f   // 2*log2(e): pre-scale so EX2 needs no mul

#define XL_BLOCKS  ((N + 255) / 256)   // 79
#define DEG_BLOCKS (E/8/256)           // 625 (exact)

// ---- cheap-path scratch (graph 7 only); self-cleaning across graph replays ----
__device__ float  d_xl[N*2];      // xl for graph-7 nodes
__device__ int    d_cnt[N];       // degree counts (zeroed inside k_finish)
__device__ float  d_acc[KEEP*2];  // tail-local accumulator (zeroed inside k_finish)
__device__ float  d_u0[KEEP], d_u1[KEEP], d_u2[KEEP];   // pre-scaled by K_SCALE

// ---- fallback scratch (full problem; zeroed at fallback start) ----
__device__ int    f_cnt[TN];
__device__ float2 f_p[TN];
__device__ float  f_acc[TN*2];
__device__ float  f_u[TN*3];

// ---------------- graph-7 xl + degree histogram (fused) ----------------
__global__ void k_deg7(const float* __restrict__ x, const float* __restrict__ Wg,
                       const int* __restrict__ ei) {
    int b = blockIdx.x;
    if (b < XL_BLOCKS) {
        int n = b * 256 + threadIdx.x;
        if (n >= N) return;
        float x0 = x[2*(7*N + n)], x1 = x[2*(7*N + n) + 1];
        d_xl[2*n]   = fmaf(x0, Wg[0], x1 * Wg[1]);
        d_xl[2*n+1] = fmaf(x0, Wg[2], x1 * Wg[3]);
    } else {
        int idx = (b - XL_BLOCKS) * 256 + threadIdx.x;   // < E/8 exactly
        const int* dp = ei + (size_t)7*2*E + E + 8*idx;
        int4 a = *reinterpret_cast<const int4*>(dp);
        int4 c = *reinterpret_cast<const int4*>(dp + 4);
        atomicAdd(&d_cnt[a.x], 1); atomicAdd(&d_cnt[a.y], 1);
        atomicAdd(&d_cnt[a.z], 1); atomicAdd(&d_cnt[a.w], 1);
        atomicAdd(&d_cnt[c.x], 1); atomicAdd(&d_cnt[c.y], 1);
        atomicAdd(&d_cnt[c.z], 1); atomicAdd(&d_cnt[c.w], 1);
    }
}

// ---------------- messages into the tail; dinv[src] computed inline ----------------
__device__ __forceinline__ void red2(float* ptr, float2 v) {
    asm volatile("red.global.add.v2.f32 [%0], {%1, %2};"
                 :: "l"(ptr), "f"(v.x), "f"(v.y) : "memory");
}

__global__ void k_msg7(const int* __restrict__ ei) {
    int idx = blockIdx.x * blockDim.x + threadIdx.x;    // < E/8 exactly
    const int* eit = ei + (size_t)7*2*E;
    int4 s0 = *reinterpret_cast<const int4*>(eit + 8*idx);
    int4 s1 = *reinterpret_cast<const int4*>(eit + 8*idx + 4);
    int4 t0 = *reinterpret_cast<const int4*>(eit + E + 8*idx);
    int4 t1 = *reinterpret_cast<const int4*>(eit + E + 8*idx + 4);
    #define EDGE(S, D) if ((D) >= NODE0) { \
        float di = rsqrtf((float)(d_cnt[(S)] + 1)); \
        float2 xl = *reinterpret_cast<const float2*>(d_xl + 2*(S)); \
        red2(d_acc + 2*((D) - NODE0), make_float2(di*xl.x, di*xl.y)); }
    EDGE(s0.x, t0.x) EDGE(s0.y, t0.y) EDGE(s0.z, t0.z) EDGE(s0.w, t0.w)
    EDGE(s1.x, t1.x) EDGE(s1.y, t1.y) EDGE(s1.z, t1.z) EDGE(s1.w, t1.w)
    #undef EDGE
}

// ---------------- scan helpers ----------------
// fast path: arg already scaled by 2*log2e -> tanh = 1 - 2*rcp(ex2(arg)+1)
__device__ __forceinline__ float tanh_e2(float a2) {
    float e; asm("ex2.approx.f32 %0, %1;" : "=f"(e) : "f"(a2));
    float d = e + 1.0f;
    float r; asm("rcp.approx.f32 %0, %1;" : "=f"(r) : "f"(d));
    return fmaf(-2.0f, r, 1.0f);
}

#define STEPS(c0, c1, c2) { \
    float a0 = fmaf(w00,h0, fmaf(w01,h1, fmaf(w02,h2, (c0)))); \
    float a1 = fmaf(w10,h0, fmaf(w11,h1, fmaf(w12,h2, (c1)))); \
    float a2 = fmaf(w20,h0, fmaf(w21,h1, fmaf(w22,h2, (c2)))); \
    h0 = tanh_e2(a0); h1 = tanh_e2(a1); h2 = tanh_e2(a2); }

#define QUADS(k) { \
    float4 a = *reinterpret_cast<const float4*>(d_u0 + (k)); \
    float4 b = *reinterpret_cast<const float4*>(d_u1 + (k)); \
    float4 u = *reinterpret_cast<const float4*>(d_u2 + (k)); \
    STEPS(a.x, b.x, u.x); STEPS(a.y, b.y, u.y); \
    STEPS(a.z, b.z, u.z); STEPS(a.w, b.w, u.w); }

// fallback step (unscaled)
__device__ __forceinline__ float tanh_fast(float x) {
    float e = __expf(2.0f * x);
    return 1.0f - __fdividef(2.0f, e + 1.0f);
}
#define STEPM(c0, c1, c2) { \
    float a0 = fmaf(v00,h0, fmaf(v01,h1, fmaf(v02,h2, (c0)))); \
    float a1 = fmaf(v10,h0, fmaf(v11,h1, fmaf(v12,h2, (c1)))); \
    float a2 = fmaf(v20,h0, fmaf(v21,h1, fmaf(v22,h2, (c2)))); \
    h0 = tanh_fast(a0); h1 = tanh_fast(a1); h2 = tanh_fast(a2); }

// ---------------- u-prep + scan + gate + output (+ full fallback) ----------------
__global__ void k_finish(const float* __restrict__ x, const int* __restrict__ ei,
                         const float* __restrict__ Wg, const float* __restrict__ bg,
                         const float* __restrict__ Wih, const float* __restrict__ Whh,
                         const float* __restrict__ bih, const float* __restrict__ bhh,
                         const float* __restrict__ Wlin, const float* __restrict__ blin,
                         float* __restrict__ out) {
    __shared__ float s_s[CHUNKS+2][3], s_b[CHUNKS][3];
    __shared__ int s_ok;
    int tid = threadIdx.x;
    int nt = blockDim.x;

    // ---- phase A: compute pre-scaled u for the 3200 tail nodes ----
    {
        float wg0=Wih[0], wg1=Wih[1], wg2=Wih[2], wg3=Wih[3], wg4=Wih[4], wg5=Wih[5];
        float c0 = (bih[0] + bhh[0]), c1 = (bih[1] + bhh[1]), c2 = (bih[2] + bhh[2]);
        float bg0 = bg[0], bg1 = bg[1];
        for (int i = tid; i < KEEP; i += nt) {
            int n = NODE0 + i;
            float dinv = rsqrtf((float)(d_cnt[n] + 1));
            float2 xl = *reinterpret_cast<const float2*>(d_xl + 2*n);
            float g0 = fmaf(dinv, fmaf(dinv, xl.x, d_acc[2*i]),   bg0);
            float g1 = fmaf(dinv, fmaf(dinv, xl.y, d_acc[2*i+1]), bg1);
            d_u0[i] = K_SCALE * fmaf(wg0, g0, fmaf(wg1, g1, c0));
            d_u1[i] = K_SCALE * fmaf(wg2, g0, fmaf(wg3, g1, c1));
            d_u2[i] = K_SCALE * fmaf(wg4, g0, fmaf(wg5, g1, c2));
        }
    }
    __syncthreads();

    // ---- phase B: chunk scan (tid < CHUNKS+2) || scratch cleanup (tid >= 128) ----
    if (tid < CHUNKS + 2) {
        float w00=K_SCALE*Whh[0], w01=K_SCALE*Whh[1], w02=K_SCALE*Whh[2];
        float w10=K_SCALE*Whh[3], w11=K_SCALE*Whh[4], w12=K_SCALE*Whh[5];
        float w20=K_SCALE*Whh[6], w21=K_SCALE*Whh[7], w22=K_SCALE*Whh[8];
        int c = (tid < CHUNKS) ? tid : 0;
        int ws = c * CLEN;                     // multiple of 4
        int k0 = ws + WARM;
        float init = (tid == CHUNKS) ? 1.f : (tid == CHUNKS+1 ? -1.f : 0.f);
        float h0 = init, h1 = init, h2 = init;
        for (int k = ws; k < k0; k += 4) QUADS(k);
        s_s[tid][0] = h0; s_s[tid][1] = h1; s_s[tid][2] = h2;
        if (tid < CHUNKS) {
            #pragma unroll 10
            for (int k = k0; k < k0 + CLEN; k += 4) QUADS(k);
            s_b[tid][0] = h0; s_b[tid][1] = h1; s_b[tid][2] = h2;
        }
    } else if (tid >= 128) {
        // self-clean scratch, hidden under the scan
        int t2 = tid - 128, n2 = nt - 128;
        for (int g = t2; g < N; g += n2) d_cnt[g] = 0;
        for (int g = t2; g < KEEP*2; g += n2) d_acc[g] = 0.f;
    }
    __syncthreads();

    if (tid == 0) {
        float md = 0.f;
        for (int c = 1; c < CHUNKS; c++)
            for (int m = 0; m < 3; m++)
                md = fmaxf(md, fabsf(s_s[c][m] - s_b[c-1][m]));
        for (int m = 0; m < 3; m++) {               // entrance insensitivity
            md = fmaxf(md, fabsf(s_s[CHUNKS][m]   - s_s[0][m]));
            md = fmaxf(md, fabsf(s_s[CHUNKS+1][m] - s_s[0][m]));
        }
        s_ok = (md < 2e-5f);
        if (s_ok) {
            float h0 = fmaxf(s_b[CHUNKS-1][0], 0.f);
            float h1 = fmaxf(s_b[CHUNKS-1][1], 0.f);
            float h2 = fmaxf(s_b[CHUNKS-1][2], 0.f);
            float z = fmaf(Wlin[0], h0, fmaf(Wlin[1], h1, fmaf(Wlin[2], h2, blin[0])));
            out[0] = 1.0f / (1.0f + expf(-z));
        }
    }
    __syncthreads();
    if (s_ok) return;

    // ================= FALLBACK: exact full computation =================
    float v00=Whh[0], v01=Whh[1], v02=Whh[2];
    float v10=Whh[3], v11=Whh[4], v12=Whh[5];
    float v20=Whh[6], v21=Whh[7], v22=Whh[8];
    for (int g = tid; g < TN; g += nt) { f_cnt[g] = 0; f_acc[2*g] = 0.f; f_acc[2*g+1] = 0.f; }
    __syncthreads();
    for (long i = tid; i < (long)T*E; i += nt) {
        int t = (int)(i / E), e = (int)(i - (long)t*E);
        int dst = ei[(size_t)t*2*E + E + e];
        atomicAdd(&f_cnt[t*N + dst], 1);
    }
    __syncthreads();
    for (int g = tid; g < TN; g += nt) {
        float x0 = x[2*g], x1 = x[2*g+1];
        float xl0 = fmaf(x0, Wg[0], x1*Wg[1]);
        float xl1 = fmaf(x0, Wg[2], x1*Wg[3]);
        float dinv = rsqrtf((float)(f_cnt[g] + 1));
        f_p[g] = make_float2(dinv * xl0, dinv * xl1);
    }
    __syncthreads();
    for (long i = tid; i < (long)T*E; i += nt) {
        int t = (int)(i / E), e = (int)(i - (long)t*E);
        const int* eit = ei + (size_t)t*2*E;
        int src = eit[e], dst = eit[E + e];
        float2 p = f_p[t*N + src];
        atomicAdd(&f_acc[2*(t*N + dst)],   p.x);
        atomicAdd(&f_acc[2*(t*N + dst)+1], p.y);
    }
    __syncthreads();
    for (int g = tid; g < TN; g += nt) {
        float dinv = rsqrtf((float)(f_cnt[g] + 1));
        float2 p = f_p[g];
        float g0 = fmaf(dinv, f_acc[2*g]   + p.x, bg[0]);
        float g1 = fmaf(dinv, f_acc[2*g+1] + p.y, bg[1]);
        f_u[3*g]   = fmaf(Wih[0], g0, fmaf(Wih[1], g1, bih[0] + bhh[0]));
        f_u[3*g+1] = fmaf(Wih[2], g0, fmaf(Wih[3], g1, bih[1] + bhh[1]));
        f_u[3*g+2] = fmaf(Wih[4], g0, fmaf(Wih[5], g1, bih[2] + bhh[2]));
    }
    __syncthreads();
    for (int g = tid; g < TN; g += nt) { f_cnt[g] = 0; f_acc[2*g] = 0.f; f_acc[2*g+1] = 0.f; }
    __syncthreads();
    if (tid == 0) {
        float h0 = 0.f, h1 = 0.f, h2 = 0.f;
        for (int k = 0; k < TN; k++) STEPM(f_u[3*k], f_u[3*k+1], f_u[3*k+2]);
        h0 = fmaxf(h0, 0.f); h1 = fmaxf(h1, 0.f); h2 = fmaxf(h2, 0.f);
        float z = fmaf(Wlin[0], h0, fmaf(Wlin[1], h1, fmaf(Wlin[2], h2, blin[0])));
        out[0] = 1.0f / (1.0f + expf(-z));
    }
}

extern "C" void kernel_launch(void* const* d_in, const int* in_sizes, int n_in,
                              void* d_out, int out_size) {
    const float* x    = (const float*)d_in[0];
    const int*   ei   = (const int*)  d_in[1];   // int32
    const float* Wg   = (const float*)d_in[2];
    const float* bg   = (const float*)d_in[3];
    const float* Wih  = (const float*)d_in[4];
    const float* Whh  = (const float*)d_in[5];
    const float* bih  = (const float*)d_in[6];
    const float* bhh  = (const float*)d_in[7];
    const float* Wlin = (const float*)d_in[8];
    const float* blin = (const float*)d_in[9];
    float* out = (float*)d_out;

    k_deg7 <<<XL_BLOCKS + DEG_BLOCKS, 256>>>(x, Wg, ei);
    k_msg7 <<<DEG_BLOCKS, 256>>>(ei);
    k_finish<<<1, 1024>>>(x, ei, Wg, bg, Wih, Whh, bih, bhh, Wlin, blin, out);
}

// round 9
// speedup vs baseline: 148.8993x; 1.0789x over previous
#include <cuda_runtime.h>
#include <math.h>

#define T 8
#define N 20000
#define E 1280000
#define TN (T*N)

#define TAILN  1280
#define CHUNKS 64
#define CLEN   20          // CHUNKS*CLEN == TAILN ; multiple of 4
#define WARM   640         // proven-safe warmup (multiple of 4)
#define KEEP   (TAILN + WARM)  // 1920 tail nodes of graph 7 need u
#define NODE0  (N - KEEP)      // 18080

#define K_SCALE 2.8853900817779268f   // 2*log2(e)

#define XL_BLOCKS  ((N + 255) / 256)   // 79
#define DEG_BLOCKS (E/8/256)           // 625 (exact)

// ---- cheap-path scratch (graph 7 only); self-cleaning across graph replays ----
__device__ float  d_xl[N*2];      // xl (fully overwritten each launch)
__device__ int    d_cnt4[4*N];    // 4-replica degree counts (zeroed in k_finish)
__device__ float  d_acc[KEEP*2];  // tail accumulator (zeroed in k_finish)
__device__ float  d_u0[KEEP], d_u1[KEEP], d_u2[KEEP];  // U = K*(u + rowsum(Whh))

// ---- fallback scratch (full problem; zeroed at fallback start) ----
__device__ int    f_cnt[TN];
__device__ float2 f_p[TN];
__device__ float  f_acc[TN*2];
__device__ float  f_u[TN*3];

__device__ __forceinline__ int cnt_of(int n) {
    return d_cnt4[n] + d_cnt4[N + n] + d_cnt4[2*N + n] + d_cnt4[3*N + n];
}

// ---------------- graph-7 xl + replicated degree histogram (fused) ----------------
__global__ void k_deg7(const float* __restrict__ x, const float* __restrict__ Wg,
                       const int* __restrict__ ei) {
    int b = blockIdx.x;
    if (b < XL_BLOCKS) {
        int n = b * 256 + threadIdx.x;
        if (n >= N) return;
        float x0 = x[2*(7*N + n)], x1 = x[2*(7*N + n) + 1];
        d_xl[2*n]   = fmaf(x0, Wg[0], x1 * Wg[1]);
        d_xl[2*n+1] = fmaf(x0, Wg[2], x1 * Wg[3]);
    } else {
        int idx = (b - XL_BLOCKS) * 256 + threadIdx.x;   // < E/8 exactly
        int rep = (threadIdx.x & 3) * N;                 // replica base
        const int* dp = ei + (size_t)7*2*E + E + 8*idx;
        int4 a = *reinterpret_cast<const int4*>(dp);
        int4 c = *reinterpret_cast<const int4*>(dp + 4);
        atomicAdd(&d_cnt4[rep + a.x], 1); atomicAdd(&d_cnt4[rep + a.y], 1);
        atomicAdd(&d_cnt4[rep + a.z], 1); atomicAdd(&d_cnt4[rep + a.w], 1);
        atomicAdd(&d_cnt4[rep + c.x], 1); atomicAdd(&d_cnt4[rep + c.y], 1);
        atomicAdd(&d_cnt4[rep + c.z], 1); atomicAdd(&d_cnt4[rep + c.w], 1);
    }
}

// ---------------- messages into the tail; dinv[src] from merged replicas ----------------
__device__ __forceinline__ void red2(float* p, float a, float b) {
    asm volatile("red.global.add.v2.f32 [%0], {%1, %2};"
                 :: "l"(p), "f"(a), "f"(b) : "memory");
}

__global__ void k_msg7(const int* __restrict__ ei) {
    int idx = blockIdx.x * blockDim.x + threadIdx.x;    // < E/8 exactly
    const int* eit = ei + (size_t)7*2*E;
    int4 s0 = *reinterpret_cast<const int4*>(eit + 8*idx);
    int4 s1 = *reinterpret_cast<const int4*>(eit + 8*idx + 4);
    int4 t0 = *reinterpret_cast<const int4*>(eit + E + 8*idx);
    int4 t1 = *reinterpret_cast<const int4*>(eit + E + 8*idx + 4);
    #define EDGE(S, D) if ((D) >= NODE0) { \
        float di = rsqrtf((float)(cnt_of(S) + 1)); \
        float2 xl = *reinterpret_cast<const float2*>(d_xl + 2*(S)); \
        red2(d_acc + 2*((D) - NODE0), di*xl.x, di*xl.y); }
    EDGE(s0.x, t0.x) EDGE(s0.y, t0.y) EDGE(s0.z, t0.z) EDGE(s0.w, t0.w)
    EDGE(s1.x, t1.x) EDGE(s1.y, t1.y) EDGE(s1.z, t1.z) EDGE(s1.w, t1.w)
    #undef EDGE
}

// ---------------- scan helpers (r-space: r = (1-h)/2, h = 1-2r) ----------------
// r' = rcp(ex2(A)+1), A = U + m00*r0 + m01*r1 + m02*r2 ; m = -2*K_SCALE*Whh
#define STEPR(c0, c1, c2) { \
    float A0 = fmaf(m00,r0, fmaf(m01,r1, fmaf(m02,r2, (c0)))); \
    float A1 = fmaf(m10,r0, fmaf(m11,r1, fmaf(m12,r2, (c1)))); \
    float A2 = fmaf(m20,r0, fmaf(m21,r1, fmaf(m22,r2, (c2)))); \
    float e0, e1, e2, q0, q1, q2; \
    asm("ex2.approx.f32 %0, %1;" : "=f"(e0) : "f"(A0)); \
    asm("ex2.approx.f32 %0, %1;" : "=f"(e1) : "f"(A1)); \
    asm("ex2.approx.f32 %0, %1;" : "=f"(e2) : "f"(A2)); \
    e0 += 1.0f; e1 += 1.0f; e2 += 1.0f; \
    asm("rcp.approx.f32 %0, %1;" : "=f"(q0) : "f"(e0)); \
    asm("rcp.approx.f32 %0, %1;" : "=f"(q1) : "f"(e1)); \
    asm("rcp.approx.f32 %0, %1;" : "=f"(q2) : "f"(e2)); \
    r0 = q0; r1 = q1; r2 = q2; }

#define QUADR(k) { \
    float4 a = *reinterpret_cast<const float4*>(d_u0 + (k)); \
    float4 b = *reinterpret_cast<const float4*>(d_u1 + (k)); \
    float4 u = *reinterpret_cast<const float4*>(d_u2 + (k)); \
    STEPR(a.x, b.x, u.x); STEPR(a.y, b.y, u.y); \
    STEPR(a.z, b.z, u.z); STEPR(a.w, b.w, u.w); }

// fallback step (unscaled, exact formulation)
__device__ __forceinline__ float tanh_fast(float x) {
    float e = __expf(2.0f * x);
    return 1.0f - __fdividef(2.0f, e + 1.0f);
}
#define STEPM(c0, c1, c2) { \
    float a0 = fmaf(v00,h0, fmaf(v01,h1, fmaf(v02,h2, (c0)))); \
    float a1 = fmaf(v10,h0, fmaf(v11,h1, fmaf(v12,h2, (c1)))); \
    float a2 = fmaf(v20,h0, fmaf(v21,h1, fmaf(v22,h2, (c2)))); \
    h0 = tanh_fast(a0); h1 = tanh_fast(a1); h2 = tanh_fast(a2); }

// ---------------- u-prep + scan + gate + output (+ full fallback) ----------------
__global__ void k_finish(const float* __restrict__ x, const int* __restrict__ ei,
                         const float* __restrict__ Wg, const float* __restrict__ bg,
                         const float* __restrict__ Wih, const float* __restrict__ Whh,
                         const float* __restrict__ bih, const float* __restrict__ bhh,
                         const float* __restrict__ Wlin, const float* __restrict__ blin,
                         float* __restrict__ out) {
    __shared__ float s_s[CHUNKS+2][3], s_b[CHUNKS][3];   // stored as h
    __shared__ int s_ok;
    int tid = threadIdx.x;
    int nt = blockDim.x;

    // ---- phase A: U = K_SCALE*(u + rowsum(Whh)) for the tail nodes ----
    {
        float wg0=Wih[0], wg1=Wih[1], wg2=Wih[2], wg3=Wih[3], wg4=Wih[4], wg5=Wih[5];
        float rs0 = Whh[0]+Whh[1]+Whh[2], rs1 = Whh[3]+Whh[4]+Whh[5], rs2 = Whh[6]+Whh[7]+Whh[8];
        float c0 = bih[0] + bhh[0] + rs0, c1 = bih[1] + bhh[1] + rs1, c2 = bih[2] + bhh[2] + rs2;
        float bg0 = bg[0], bg1 = bg[1];
        for (int i = tid; i < KEEP; i += nt) {
            int n = NODE0 + i;
            float dinv = rsqrtf((float)(cnt_of(n) + 1));
            float2 xl = *reinterpret_cast<const float2*>(d_xl + 2*n);
            float g0 = fmaf(dinv, fmaf(dinv, xl.x, d_acc[2*i]),   bg0);
            float g1 = fmaf(dinv, fmaf(dinv, xl.y, d_acc[2*i+1]), bg1);
            d_u0[i] = K_SCALE * fmaf(wg0, g0, fmaf(wg1, g1, c0));
            d_u1[i] = K_SCALE * fmaf(wg2, g0, fmaf(wg3, g1, c1));
            d_u2[i] = K_SCALE * fmaf(wg4, g0, fmaf(wg5, g1, c2));
        }
    }
    __syncthreads();

    // ---- phase B: chunk scan (tid < CHUNKS+2) || scratch cleanup (tid >= 128) ----
    if (tid < CHUNKS + 2) {
        float m00=-2.f*K_SCALE*Whh[0], m01=-2.f*K_SCALE*Whh[1], m02=-2.f*K_SCALE*Whh[2];
        float m10=-2.f*K_SCALE*Whh[3], m11=-2.f*K_SCALE*Whh[4], m12=-2.f*K_SCALE*Whh[5];
        float m20=-2.f*K_SCALE*Whh[6], m21=-2.f*K_SCALE*Whh[7], m22=-2.f*K_SCALE*Whh[8];
        int c = (tid < CHUNKS) ? tid : 0;
        int ws = c * CLEN;                 // multiple of 4
        int k0 = ws + WARM;
        // h=0 -> r=0.5 ; h=+1 -> r=0 ; h=-1 -> r=1
        float init = (tid == CHUNKS) ? 0.f : (tid == CHUNKS+1 ? 1.f : 0.5f);
        float r0 = init, r1 = init, r2 = init;
        for (int k = ws; k < k0; k += 4) QUADR(k);
        s_s[tid][0] = fmaf(-2.f, r0, 1.f);
        s_s[tid][1] = fmaf(-2.f, r1, 1.f);
        s_s[tid][2] = fmaf(-2.f, r2, 1.f);
        if (tid < CHUNKS) {
            #pragma unroll 5
            for (int k = k0; k < k0 + CLEN; k += 4) QUADR(k);
            s_b[tid][0] = fmaf(-2.f, r0, 1.f);
            s_b[tid][1] = fmaf(-2.f, r1, 1.f);
            s_b[tid][2] = fmaf(-2.f, r2, 1.f);
        }
    } else if (tid >= 128) {
        // self-clean scratch, hidden under the scan
        int t2 = tid - 128, n2 = nt - 128;
        for (int g = t2; g < 4*N;    g += n2) d_cnt4[g] = 0;
        for (int g = t2; g < KEEP*2; g += n2) d_acc[g] = 0.f;
    }
    __syncthreads();

    if (tid == 0) {
        float md = 0.f;
        for (int c = 1; c < CHUNKS; c++)
            for (int m = 0; m < 3; m++)
                md = fmaxf(md, fabsf(s_s[c][m] - s_b[c-1][m]));
        for (int m = 0; m < 3; m++) {               // entrance insensitivity
            md = fmaxf(md, fabsf(s_s[CHUNKS][m]   - s_s[0][m]));
            md = fmaxf(md, fabsf(s_s[CHUNKS+1][m] - s_s[0][m]));
        }
        s_ok = (md < 2e-5f);
        if (s_ok) {
            float h0 = fmaxf(s_b[CHUNKS-1][0], 0.f);
            float h1 = fmaxf(s_b[CHUNKS-1][1], 0.f);
            float h2 = fmaxf(s_b[CHUNKS-1][2], 0.f);
            float z = fmaf(Wlin[0], h0, fmaf(Wlin[1], h1, fmaf(Wlin[2], h2, blin[0])));
            out[0] = 1.0f / (1.0f + expf(-z));
        }
    }
    __syncthreads();
    if (s_ok) return;

    // ================= FALLBACK: exact full computation =================
    float v00=Whh[0], v01=Whh[1], v02=Whh[2];
    float v10=Whh[3], v11=Whh[4], v12=Whh[5];
    float v20=Whh[6], v21=Whh[7], v22=Whh[8];
    for (int g = tid; g < TN; g += nt) { f_cnt[g] = 0; f_acc[2*g] = 0.f; f_acc[2*g+1] = 0.f; }
    __syncthreads();
    for (long i = tid; i < (long)T*E; i += nt) {
        int t = (int)(i / E), e = (int)(i - (long)t*E);
        int dst = ei[(size_t)t*2*E + E + e];
        atomicAdd(&f_cnt[t*N + dst], 1);
    }
    __syncthreads();
    for (int g = tid; g < TN; g += nt) {
        float x0 = x[2*g], x1 = x[2*g+1];
        float xl0 = fmaf(x0, Wg[0], x1*Wg[1]);
        float xl1 = fmaf(x0, Wg[2], x1*Wg[3]);
        float dinv = rsqrtf((float)(f_cnt[g] + 1));
        f_p[g] = make_float2(dinv * xl0, dinv * xl1);
    }
    __syncthreads();
    for (long i = tid; i < (long)T*E; i += nt) {
        int t = (int)(i / E), e = (int)(i - (long)t*E);
        const int* et2 = ei + (size_t)t*2*E;
        int src = et2[e], dst = et2[E + e];
        float2 p = f_p[t*N + src];
        atomicAdd(&f_acc[2*(t*N + dst)],   p.x);
        atomicAdd(&f_acc[2*(t*N + dst)+1], p.y);
    }
    __syncthreads();
    for (int g = tid; g < TN; g += nt) {
        float dinv = rsqrtf((float)(f_cnt[g] + 1));
        float2 p = f_p[g];
        float g0 = fmaf(dinv, f_acc[2*g]   + p.x, bg[0]);
        float g1 = fmaf(dinv, f_acc[2*g+1] + p.y, bg[1]);
        f_u[3*g]   = fmaf(Wih[0], g0, fmaf(Wih[1], g1, bih[0] + bhh[0]));
        f_u[3*g+1] = fmaf(Wih[2], g0, fmaf(Wih[3], g1, bih[1] + bhh[1]));
        f_u[3*g+2] = fmaf(Wih[4], g0, fmaf(Wih[5], g1, bih[2] + bhh[2]));
    }
    __syncthreads();
    for (int g = tid; g < TN; g += nt) { f_cnt[g] = 0; f_acc[2*g] = 0.f; f_acc[2*g+1] = 0.f; }
    __syncthreads();
    if (tid == 0) {
        float h0 = 0.f, h1 = 0.f, h2 = 0.f;
        for (int k = 0; k < TN; k++) STEPM(f_u[3*k], f_u[3*k+1], f_u[3*k+2]);
        h0 = fmaxf(h0, 0.f); h1 = fmaxf(h1, 0.f); h2 = fmaxf(h2, 0.f);
        float z = fmaf(Wlin[0], h0, fmaf(Wlin[1], h1, fmaf(Wlin[2], h2, blin[0])));
        out[0] = 1.0f / (1.0f + expf(-z));
    }
}

extern "C" void kernel_launch(void* const* d_in, const int* in_sizes, int n_in,
                              void* d_out, int out_size) {
    const float* x    = (const float*)d_in[0];
    const int*   ei   = (const int*)  d_in[1];   // int32
    const float* Wg   = (const float*)d_in[2];
    const float* bg   = (const float*)d_in[3];
    const float* Wih  = (const float*)d_in[4];
    const float* Whh  = (const float*)d_in[5];
    const float* bih  = (const float*)d_in[6];
    const float* bhh  = (const float*)d_in[7];
    const float* Wlin = (const float*)d_in[8];
    const float* blin = (const float*)d_in[9];
    float* out = (float*)d_out;

    k_deg7 <<<XL_BLOCKS + DEG_BLOCKS, 256>>>(x, Wg, ei);
    k_msg7 <<<DEG_BLOCKS, 256>>>(ei);
    k_finish<<<1, 1024>>>(x, ei, Wg, bg, Wih, Whh, bih, bhh, Wlin, blin, out);
}